// round 4
// baseline (speedup 1.0000x reference)
#include <cuda_runtime.h>
#include <cuda_bf16.h>
#include <math.h>

#define NXc 512
#define NQc 512
#define NUc 128
#define B_SZ 32768
#define KXU 640
#define EPSc 0.001f
#define NEWTON_ITERS 20

// ---------------- device scratch (static, no allocations) ----------------
__device__ float g_P[NXc * NXc];
__device__ float g_T[NXc * NXc];
__device__ float g_Xa[NXc * NXc];
__device__ float g_Xb[NXc * NXc];
__device__ float g_H1[NXc * NXc];
__device__ float g_H2[NXc * NXc];
__device__ float g_H4[NQc * NQc];
__device__ float g_Y[NXc * NXc];
__device__ float g_Mm[NXc * NQc];
__device__ float g_D11[NQc * NQc];
__device__ float g_Am[NXc * NXc];
__device__ float g_B1m[NXc * NQc];
__device__ float g_CD[NQc * KXU];
__device__ float g_AB2[NXc * KXU];
__device__ float g_rlam[NQc];
__device__ float g_xu[(size_t)B_SZ * KXU];
__device__ float g_baseT[(size_t)NQc * B_SZ];
__device__ float g_wT[(size_t)NQc * B_SZ];
__device__ unsigned int g_snorm_bits;

// ---------------- generic fp32 tiled GEMM ----------------
// C(MxN) = alpha * op(A) * op(B) + beta * C
template <int BM, int BN, int BK, int TM, int TN, bool TRA, bool TRB>
__global__ __launch_bounds__((BM / TM) * (BN / TN))
void sgemm_kernel(int M, int N, int K,
                  const float* __restrict__ A, int lda,
                  const float* __restrict__ B, int ldb,
                  float* __restrict__ C, int ldc,
                  float alpha, float beta) {
    __shared__ float As[BK][BM + 4];
    __shared__ float Bs[BK][BN + 4];
    constexpr int THREADS = (BM / TM) * (BN / TN);
    const int t = threadIdx.x;
    const int tx = t % (BN / TN);
    const int ty = t / (BN / TN);
    const int m0 = blockIdx.y * BM;
    const int n0 = blockIdx.x * BN;

    float acc[TM][TN];
#pragma unroll
    for (int i = 0; i < TM; i++)
#pragma unroll
        for (int j = 0; j < TN; j++) acc[i][j] = 0.f;

    for (int k0 = 0; k0 < K; k0 += BK) {
        if (!TRA) {
#pragma unroll
            for (int idx = t; idx < BM * BK; idx += THREADS) {
                int i = idx / BK, j = idx % BK;
                As[j][i] = A[(size_t)(m0 + i) * lda + (k0 + j)];
            }
        } else {
#pragma unroll
            for (int idx = t; idx < BM * BK; idx += THREADS) {
                int i = idx % BM, j = idx / BM;
                As[j][i] = A[(size_t)(k0 + j) * lda + (m0 + i)];
            }
        }
        if (!TRB) {
#pragma unroll
            for (int idx = t; idx < BK * BN; idx += THREADS) {
                int i = idx % BN, j = idx / BN;
                Bs[j][i] = B[(size_t)(k0 + j) * ldb + (n0 + i)];
            }
        } else {
#pragma unroll
            for (int idx = t; idx < BK * BN; idx += THREADS) {
                int j = idx % BK, i = idx / BK;
                Bs[j][i] = B[(size_t)(n0 + i) * ldb + (k0 + j)];
            }
        }
        __syncthreads();
#pragma unroll
        for (int kk = 0; kk < BK; kk++) {
            float ra[TM], rb[TN];
#pragma unroll
            for (int i = 0; i < TM; i++) ra[i] = As[kk][ty * TM + i];
#pragma unroll
            for (int j = 0; j < TN; j++) rb[j] = Bs[kk][tx * TN + j];
#pragma unroll
            for (int i = 0; i < TM; i++)
#pragma unroll
                for (int j = 0; j < TN; j++)
                    acc[i][j] = fmaf(ra[i], rb[j], acc[i][j]);
        }
        __syncthreads();
    }
#pragma unroll
    for (int i = 0; i < TM; i++) {
#pragma unroll
        for (int j = 0; j < TN; j++) {
            size_t off = (size_t)(m0 + ty * TM + i) * ldc + (n0 + tx * TN + j);
            float v = alpha * acc[i][j];
            if (beta != 0.f) v = fmaf(beta, C[off], v);
            C[off] = v;
        }
    }
}

// ---------------- compensated P = 0.5*Pstar@Pstar^T + EPS*I ----------------
__global__ __launch_bounds__(256)
void pgemm_dot2_kernel(const float* __restrict__ Ps, float* __restrict__ P) {
    __shared__ float As[16][68];
    __shared__ float Bs[16][68];
    const int t = threadIdx.x;
    const int tx = t % 16;
    const int ty = t / 16;
    const int m0 = blockIdx.y * 64;
    const int n0 = blockIdx.x * 64;
    float s[4][4], cmp[4][4];
#pragma unroll
    for (int i = 0; i < 4; i++)
#pragma unroll
        for (int j = 0; j < 4; j++) { s[i][j] = 0.f; cmp[i][j] = 0.f; }

    for (int k0 = 0; k0 < NXc; k0 += 16) {
#pragma unroll
        for (int idx = t; idx < 64 * 16; idx += 256) {
            int i = idx / 16, j = idx % 16;
            As[j][i] = Ps[(size_t)(m0 + i) * NXc + k0 + j];
            Bs[j][i] = Ps[(size_t)(n0 + i) * NXc + k0 + j];
        }
        __syncthreads();
#pragma unroll
        for (int kk = 0; kk < 16; kk++) {
            float ra[4], rb[4];
#pragma unroll
            for (int i = 0; i < 4; i++) ra[i] = As[kk][ty * 4 + i];
#pragma unroll
            for (int j = 0; j < 4; j++) rb[j] = Bs[kk][tx * 4 + j];
#pragma unroll
            for (int i = 0; i < 4; i++)
#pragma unroll
                for (int j = 0; j < 4; j++) {
                    float p = ra[i] * rb[j];
                    float e = fmaf(ra[i], rb[j], -p);
                    float t1 = s[i][j] + p;
                    float z = t1 - s[i][j];
                    float e2 = (s[i][j] - (t1 - z)) + (p - z);
                    s[i][j] = t1;
                    cmp[i][j] += e + e2;
                }
        }
        __syncthreads();
    }
#pragma unroll
    for (int i = 0; i < 4; i++)
#pragma unroll
        for (int j = 0; j < 4; j++) {
            int r = m0 + ty * 4 + i, c = n0 + tx * 4 + j;
            float v = 0.5f * (s[i][j] + cmp[i][j]);
            if (r == c) v += EPSc;
            P[(size_t)r * NXc + c] = v;
        }
}

// ---------------- elementwise helpers ----------------
__global__ void k_zero_snorm() { g_snorm_bits = 0u; }

__global__ void k_rowsum(const float* __restrict__ P) {
    __shared__ float sm[128];
    int r = blockIdx.x;
    float s = 0.f;
    for (int j = threadIdx.x; j < NXc; j += 128) s += fabsf(P[(size_t)r * NXc + j]);
    sm[threadIdx.x] = s;
    __syncthreads();
    for (int o = 64; o > 0; o >>= 1) {
        if (threadIdx.x < o) sm[threadIdx.x] += sm[threadIdx.x + o];
        __syncthreads();
    }
    if (threadIdx.x == 0) atomicMax(&g_snorm_bits, __float_as_uint(sm[0]));
}

__global__ void k_newton_init(const float* __restrict__ P, float* __restrict__ Xa) {
    int idx = blockIdx.x * 256 + threadIdx.x;
    float a = 1.f / __uint_as_float(g_snorm_bits);
    int i = idx >> 9, j = idx & 511;
    float v = -a * a * P[idx];
    if (i == j) v += 2.f * a;
    Xa[idx] = v;
}

__global__ void k_two_minus(float* __restrict__ T) {
    int idx = blockIdx.x * 256 + threadIdx.x;
    int i = idx >> 9, j = idx & 511;
    T[idx] = (i == j ? 2.f : 0.f) - T[idx];
}

__global__ void k_build_Y(const float* __restrict__ H1, const float* __restrict__ Y1,
                          float* __restrict__ Y) {
    int idx = blockIdx.x * 256 + threadIdx.x;
    int i = idx >> 9, j = idx & 511;
    float v = H1[idx] + Y1[idx] - Y1[(size_t)j * NXc + i];
    if (i == j) v += EPSc;
    Y[idx] = -0.5f * v;
}

__global__ void k_rlam(const float* __restrict__ H4, float* __restrict__ rlam) {
    int i = blockIdx.x * 256 + threadIdx.x;
    if (i < NQc) rlam[i] = 1.f / (0.5f * (H4[(size_t)i * NQc + i] + EPSc));
}

__global__ void k_D11(const float* __restrict__ H4, const float* __restrict__ rlam,
                      float* __restrict__ D11) {
    int idx = blockIdx.x * 256 + threadIdx.x;
    int i = idx >> 9, j = idx & 511;
    D11[idx] = (j < i) ? (-H4[idx] * rlam[i]) : 0.f;
}

__global__ void k_build_M(const float* __restrict__ H2, const float* __restrict__ Chi,
                          float* __restrict__ Mm) {
    int idx = blockIdx.x * 256 + threadIdx.x;
    Mm[idx] = -H2[idx] - Chi[idx];
}

__global__ void k_build_CD(const float* __restrict__ Chi, const float* __restrict__ D12,
                           const float* __restrict__ rlam, float* __restrict__ CD) {
    int q = blockIdx.x, k = threadIdx.x;
    float v = (k < NXc) ? Chi[(size_t)k * NQc + q] * rlam[q]
                        : D12[(size_t)q * NUc + (k - NXc)];
    CD[(size_t)q * KXU + k] = v;
}

__global__ void k_build_AB2(const float* __restrict__ A, const float* __restrict__ B2,
                            float* __restrict__ AB2) {
    int x = blockIdx.x, k = threadIdx.x;
    float v = (k < NXc) ? A[(size_t)x * NXc + k]
                        : B2[(size_t)x * NUc + (k - NXc)];
    AB2[(size_t)x * KXU + k] = v;
}

__global__ void k_build_xu(const float* __restrict__ xi, const float* __restrict__ u,
                           float* __restrict__ xu) {
    size_t idx = (size_t)blockIdx.x * 256 + threadIdx.x;
    int b = (int)(idx / KXU), k = (int)(idx % KXU);
    xu[idx] = (k < NXc) ? xi[(size_t)b * NXc + k] : u[(size_t)b * NUc + (k - NXc)];
}

// ---------------- within-chunk sequential tanh scan ----------------
__global__ __launch_bounds__(256)
void k_scan(const float* __restrict__ baseT, float* __restrict__ wT,
            const float* __restrict__ D11, int c) {
    __shared__ float d[64][65];
    const int tid = threadIdx.x;
    const size_t b = (size_t)blockIdx.x * 256 + tid;
    const int r0 = c * 64;
    for (int idx = tid; idx < 4096; idx += 256) {
        int i = idx >> 6, j = idx & 63;
        d[i][j] = D11[(size_t)(r0 + i) * NQc + r0 + j];
    }
    __syncthreads();
    float w[64];
#pragma unroll
    for (int i = 0; i < 64; i++) {
        size_t off = (size_t)(r0 + i) * B_SZ + b;
        float v = baseT[off];
        if (c > 0) v += wT[off];  // cross-chunk partial (GEMM result)
        float s0 = 0.f, s1 = 0.f, s2 = 0.f, s3 = 0.f;
#pragma unroll
        for (int j = 0; j + 3 < i; j += 4) {
            s0 = fmaf(w[j],     d[i][j],     s0);
            s1 = fmaf(w[j + 1], d[i][j + 1], s1);
            s2 = fmaf(w[j + 2], d[i][j + 2], s2);
            s3 = fmaf(w[j + 3], d[i][j + 3], s3);
        }
#pragma unroll
        for (int j = i & ~3; j < i; j++) s0 = fmaf(w[j], d[i][j], s0);
        v += (s0 + s1) + (s2 + s3);
        v = tanhf(v);
        w[i] = v;
        wT[off] = v;
    }
}

// ---------------- host-side launch helpers ----------------
template <int BM, int BN, int BK, int TM, int TN, bool TRA, bool TRB>
static void launch_gemm(int M, int N, int K,
                        const float* A, int lda, const float* B, int ldb,
                        float* C, int ldc, float alpha, float beta) {
    dim3 grid(N / BN, M / BM);
    sgemm_kernel<BM, BN, BK, TM, TN, TRA, TRB>
        <<<grid, (BM / TM) * (BN / TN)>>>(M, N, K, A, lda, B, ldb, C, ldc, alpha, beta);
}

#define G64(TRA, TRB)   launch_gemm<64, 64, 16, 4, 4, TRA, TRB>
#define G64W(TRA, TRB)  launch_gemm<64, 128, 16, 4, 8, TRA, TRB>
#define G128(TRA, TRB)  launch_gemm<128, 128, 16, 8, 8, TRA, TRB>

static float* sym(const void* symbol) {
    void* p = nullptr;
    cudaGetSymbolAddress(&p, symbol);
    return (float*)p;
}

extern "C" void kernel_launch(void* const* d_in, const int* in_sizes, int n_in,
                              void* d_out, int out_size) {
    const float* xi    = (const float*)d_in[1];
    const float* u     = (const float*)d_in[2];
    const float* Pstar = (const float*)d_in[3];
    const float* Chi   = (const float*)d_in[4];
    const float* Y1    = (const float*)d_in[5];
    const float* B2    = (const float*)d_in[6];
    const float* D12   = (const float*)d_in[7];
    const float* X     = (const float*)d_in[8];
    float* out = (float*)d_out;

    float* P   = sym(g_P);
    float* T   = sym(g_T);
    float* Xa  = sym(g_Xa);
    float* Xb  = sym(g_Xb);
    float* H1  = sym(g_H1);
    float* H2  = sym(g_H2);
    float* H4  = sym(g_H4);
    float* Y   = sym(g_Y);
    float* Mm  = sym(g_Mm);
    float* D11 = sym(g_D11);
    float* Am  = sym(g_Am);
    float* B1m = sym(g_B1m);
    float* CD  = sym(g_CD);
    float* AB2 = sym(g_AB2);
    float* rlam = sym(g_rlam);
    float* xu  = sym(g_xu);
    float* baseT = sym(g_baseT);
    float* wT  = sym(g_wT);

    // ---- P (compensated) ----
    pgemm_dot2_kernel<<<dim3(8, 8), 256>>>(Pstar, P);

    // ---- ||P||_inf, Newton-Schulz seed + iterations ----
    k_zero_snorm<<<1, 1>>>();
    k_rowsum<<<NXc, 128>>>(P);
    k_newton_init<<<1024, 256>>>(P, Xa);
    float* Xc = Xa;
    float* Xn = Xb;
    for (int it = 0; it < NEWTON_ITERS; it++) {
        G64(false, false)(NXc, NXc, NXc, P, NXc, Xc, NXc, T, NXc, 1.f, 0.f);
        k_two_minus<<<1024, 256>>>(T);
        G64(false, false)(NXc, NXc, NXc, Xc, NXc, T, NXc, Xn, NXc, 1.f, 0.f);
        float* tmp = Xc; Xc = Xn; Xn = tmp;
    }
    // Pinv = Xc

    // ---- H blocks from X (1024x1024) ----
    const float* Xlo = X + (size_t)NXc * (NXc + NQc);
    G64(false, true)(NXc, NXc, NXc + NQc, X, NXc + NQc, X, NXc + NQc, H1, NXc, 1.f, 0.f);
    G64(false, true)(NXc, NQc, NXc + NQc, X, NXc + NQc, Xlo, NXc + NQc, H2, NQc, 1.f, 0.f);
    G64(false, true)(NQc, NQc, NXc + NQc, Xlo, NXc + NQc, Xlo, NXc + NQc, H4, NQc, 1.f, 0.f);

    // ---- derived small matrices ----
    k_build_Y<<<1024, 256>>>(H1, Y1, Y);
    k_rlam<<<2, 256>>>(H4, rlam);
    k_D11<<<1024, 256>>>(H4, rlam, D11);
    k_build_M<<<1024, 256>>>(H2, Chi, Mm);
    G64(false, false)(NXc, NXc, NXc, Xc, NXc, Y, NXc, Am, NXc, 1.f, 0.f);
    G64(false, false)(NXc, NQc, NXc, Xc, NXc, Mm, NQc, B1m, NQc, 1.f, 0.f);
    k_build_CD<<<NQc, KXU>>>(Chi, D12, rlam, CD);
    k_build_AB2<<<NXc, KXU>>>(Am, B2, AB2);

    // ---- batched path ----
    k_build_xu<<<(B_SZ * KXU) / 256, 256>>>(xi, u, xu);

    // baseT[q][b] = sum_k CD[q][k] * xu[b][k]
    G128(false, true)(NQc, B_SZ, KXU, CD, KXU, xu, KXU, baseT, B_SZ, 1.f, 0.f);

    // ---- chunked recurrence: 8 chunks of 64 ----
    for (int c = 0; c < 8; c++) {
        if (c > 0) {
            // cross-chunk: wT[c*64 .. c*64+64) pre = D11[c*64..][0..c*64) @ wT[0..c*64)
            G64W(false, false)(64, B_SZ, c * 64,
                               D11 + (size_t)c * 64 * NQc, NQc,
                               wT, B_SZ,
                               wT + (size_t)c * 64 * B_SZ, B_SZ, 1.f, 0.f);
        }
        k_scan<<<B_SZ / 256, 256>>>(baseT, wT, D11, c);
    }

    // ---- output: out = xu @ AB2^T + wT^T @ B1^T ----
    G128(false, true)(B_SZ, NXc, KXU, xu, KXU, AB2, KXU, out, NXc, 1.f, 0.f);
    G128(true, true)(B_SZ, NXc, NQc, wT, B_SZ, B1m, NXc, out, NXc, 1.f, 1.f);
}

// round 13
// speedup vs baseline: 1.3377x; 1.3377x over previous
#include <cuda_runtime.h>
#include <cuda_bf16.h>
#include <math.h>

#define NXc 512
#define NQc 512
#define NUc 128
#define B_SZ 32768
#define KXU 640
#define EPSc 0.001f
#define NN (NXc * NXc)
#define NEWTON_ITERS 16
#define NPOW 12

// ---------------- device scratch (static, no allocations) ----------------
__device__ float g_P[NN];
__device__ float g_T2[2 * NN];          // split-K partials of T = P*X
__device__ float g_NXa[2 * NN];         // Newton X ping (2 partials)
__device__ float g_NXb[2 * NN];         // Newton X pong (2 partials)
__device__ float g_Pinv[NN];
__device__ float g_H12[NXc * 1024];     // [H1 | H2]
__device__ float g_H4[NN];
__device__ float g_YM[NXc * 1024];      // [Y | M]
__device__ float g_AmB1[NXc * 1024];    // [A | B1]
__device__ float g_D11[NQc * NQc];
__device__ float g_CD[NQc * KXU];
__device__ float g_AB2[NXc * KXU];
__device__ float g_rlam[NQc];
__device__ float g_xu[(size_t)B_SZ * KXU];
__device__ float g_baseT[(size_t)NQc * B_SZ];
__device__ float g_wT[(size_t)NQc * B_SZ];
__device__ float g_pv[NXc];
__device__ float g_pw[NXc];
__device__ float g_lam[1];

// ---------------- generic fp32 tiled GEMM with register prefetch ----------------
// C(MxN) = alpha * op(A) * op(B) + beta * C
template <int BM, int BN, int BK, int TM, int TN, bool TRA, bool TRB>
__global__ __launch_bounds__((BM / TM) * (BN / TN))
void sgemm_kernel(int M, int N, int K,
                  const float* __restrict__ A, int lda,
                  const float* __restrict__ B, int ldb,
                  float* __restrict__ C, int ldc,
                  float alpha, float beta) {
    constexpr int THREADS = (BM / TM) * (BN / TN);
    constexpr int LA = BM * BK / THREADS;
    constexpr int LB = BK * BN / THREADS;
    __shared__ float As[BK][BM + 4];
    __shared__ float Bs[BK][BN + 4];
    const int t = threadIdx.x;
    const int tx = t % (BN / TN);
    const int ty = t / (BN / TN);
    const int m0 = blockIdx.y * BM;
    const int n0 = blockIdx.x * BN;

    float acc[TM][TN];
#pragma unroll
    for (int i = 0; i < TM; i++)
#pragma unroll
        for (int j = 0; j < TN; j++) acc[i][j] = 0.f;

    float pa[LA], pb[LB];

    auto fetch = [&](int k0) {
#pragma unroll
        for (int l = 0; l < LA; l++) {
            int idx = t + l * THREADS;
            if (!TRA) {
                int i = idx / BK, j = idx % BK;
                pa[l] = A[(size_t)(m0 + i) * lda + (k0 + j)];
            } else {
                int i = idx % BM, j = idx / BM;
                pa[l] = A[(size_t)(k0 + j) * lda + (m0 + i)];
            }
        }
#pragma unroll
        for (int l = 0; l < LB; l++) {
            int idx = t + l * THREADS;
            if (!TRB) {
                int i = idx % BN, j = idx / BN;
                pb[l] = B[(size_t)(k0 + j) * ldb + (n0 + i)];
            } else {
                int j = idx % BK, i = idx / BK;
                pb[l] = B[(size_t)(n0 + i) * ldb + (k0 + j)];
            }
        }
    };
    auto store_smem = [&]() {
#pragma unroll
        for (int l = 0; l < LA; l++) {
            int idx = t + l * THREADS;
            int i, j;
            if (!TRA) { i = idx / BK; j = idx % BK; }
            else      { i = idx % BM; j = idx / BM; }
            As[j][i] = pa[l];
        }
#pragma unroll
        for (int l = 0; l < LB; l++) {
            int idx = t + l * THREADS;
            int i, j;
            if (!TRB) { i = idx % BN; j = idx / BN; }
            else      { j = idx % BK; i = idx / BK; }
            Bs[j][i] = pb[l];
        }
    };
    auto compute = [&]() {
#pragma unroll
        for (int kk = 0; kk < BK; kk++) {
            float ra[TM], rb[TN];
#pragma unroll
            for (int i = 0; i < TM; i++) ra[i] = As[kk][ty * TM + i];
#pragma unroll
            for (int j = 0; j < TN; j++) rb[j] = Bs[kk][tx * TN + j];
#pragma unroll
            for (int i = 0; i < TM; i++)
#pragma unroll
                for (int j = 0; j < TN; j++)
                    acc[i][j] = fmaf(ra[i], rb[j], acc[i][j]);
        }
    };

    fetch(0);
    store_smem();
    __syncthreads();
    for (int k0 = BK; k0 < K; k0 += BK) {
        fetch(k0);       // global loads in flight while computing current tile
        compute();
        __syncthreads();
        store_smem();
        __syncthreads();
    }
    compute();

#pragma unroll
    for (int i = 0; i < TM; i++) {
#pragma unroll
        for (int j = 0; j < TN; j++) {
            size_t off = (size_t)(m0 + ty * TM + i) * ldc + (n0 + tx * TN + j);
            float v = alpha * acc[i][j];
            if (beta != 0.f) v = fmaf(beta, C[off], v);
            C[off] = v;
        }
    }
}

// ---------------- Newton GEMM: 64x64 tile, split-K=2, fused operand combine ----
// COMBA=false: A = A0 (P).          COMBA=true: A = A0 + A1 (X partials)
// DIAG2=false: B = B0 + B1 (X).     DIAG2=true: B = 2I - B0 - B1 (T partials)
// C partial z written to C + z*NN.
template <bool COMBA, bool DIAG2>
__global__ __launch_bounds__(256)
void newton_gemm(const float* __restrict__ A0, const float* __restrict__ A1,
                 const float* __restrict__ B0, const float* __restrict__ B1,
                 float* __restrict__ C) {
    __shared__ float As[16][68];
    __shared__ float Bs[16][68];
    const int t = threadIdx.x;
    const int tx = t % 16, ty = t / 16;
    const int m0 = blockIdx.y * 64;
    const int n0 = blockIdx.x * 64;
    const int kbase = blockIdx.z * 256;
    float acc[4][4];
#pragma unroll
    for (int i = 0; i < 4; i++)
#pragma unroll
        for (int j = 0; j < 4; j++) acc[i][j] = 0.f;

    float pa[4], pb[4];
    auto fetch = [&](int k0) {
#pragma unroll
        for (int l = 0; l < 4; l++) {
            int idx = t + l * 256;
            int i = idx / 16, j = idx % 16;
            int ka = kbase + k0 + j;
            float a = A0[(size_t)(m0 + i) * NXc + ka];
            if (COMBA) a += A1[(size_t)(m0 + i) * NXc + ka];
            pa[l] = a;
        }
#pragma unroll
        for (int l = 0; l < 4; l++) {
            int idx = t + l * 256;
            int i = idx % 64, j = idx / 64;
            int kb = kbase + k0 + j;
            size_t off = (size_t)kb * NXc + (n0 + i);
            float b;
            if (DIAG2) {
                b = -B0[off] - B1[off];
                if (kb == n0 + i) b += 2.f;
            } else {
                b = B0[off] + B1[off];
            }
            pb[l] = b;
        }
    };
    auto store_smem = [&]() {
#pragma unroll
        for (int l = 0; l < 4; l++) {
            int idx = t + l * 256;
            As[idx % 16][idx / 16] = pa[l];
        }
#pragma unroll
        for (int l = 0; l < 4; l++) {
            int idx = t + l * 256;
            Bs[idx / 64][idx % 64] = pb[l];
        }
    };
    auto compute = [&]() {
#pragma unroll
        for (int kk = 0; kk < 16; kk++) {
            float ra[4], rb[4];
#pragma unroll
            for (int i = 0; i < 4; i++) ra[i] = As[kk][ty * 4 + i];
#pragma unroll
            for (int j = 0; j < 4; j++) rb[j] = Bs[kk][tx * 4 + j];
#pragma unroll
            for (int i = 0; i < 4; i++)
#pragma unroll
                for (int j = 0; j < 4; j++)
                    acc[i][j] = fmaf(ra[i], rb[j], acc[i][j]);
        }
    };

    fetch(0);
    store_smem();
    __syncthreads();
    for (int k0 = 16; k0 < 256; k0 += 16) {
        fetch(k0);
        compute();
        __syncthreads();
        store_smem();
        __syncthreads();
    }
    compute();

    float* Cz = C + (size_t)blockIdx.z * NN;
#pragma unroll
    for (int i = 0; i < 4; i++)
#pragma unroll
        for (int j = 0; j < 4; j++)
            Cz[(size_t)(m0 + ty * 4 + i) * NXc + (n0 + tx * 4 + j)] = acc[i][j];
}

// ---------------- compensated P = 0.5*Pstar@Pstar^T + EPS*I ----------------
__global__ __launch_bounds__(256)
void pgemm_dot2_kernel(const float* __restrict__ Ps, float* __restrict__ P) {
    __shared__ float As[16][68];
    __shared__ float Bs[16][68];
    const int t = threadIdx.x;
    const int tx = t % 16, ty = t / 16;
    const int m0 = blockIdx.y * 64;
    const int n0 = blockIdx.x * 64;
    float s[4][4], cmp[4][4];
#pragma unroll
    for (int i = 0; i < 4; i++)
#pragma unroll
        for (int j = 0; j < 4; j++) { s[i][j] = 0.f; cmp[i][j] = 0.f; }

    for (int k0 = 0; k0 < NXc; k0 += 16) {
#pragma unroll
        for (int idx = t; idx < 64 * 16; idx += 256) {
            int i = idx / 16, j = idx % 16;
            As[j][i] = Ps[(size_t)(m0 + i) * NXc + k0 + j];
            Bs[j][i] = Ps[(size_t)(n0 + i) * NXc + k0 + j];
        }
        __syncthreads();
#pragma unroll
        for (int kk = 0; kk < 16; kk++) {
            float ra[4], rb[4];
#pragma unroll
            for (int i = 0; i < 4; i++) ra[i] = As[kk][ty * 4 + i];
#pragma unroll
            for (int j = 0; j < 4; j++) rb[j] = Bs[kk][tx * 4 + j];
#pragma unroll
            for (int i = 0; i < 4; i++)
#pragma unroll
                for (int j = 0; j < 4; j++) {
                    float p = ra[i] * rb[j];
                    float e = fmaf(ra[i], rb[j], -p);
                    float t1 = s[i][j] + p;
                    float z = t1 - s[i][j];
                    float e2 = (s[i][j] - (t1 - z)) + (p - z);
                    s[i][j] = t1;
                    cmp[i][j] += e + e2;
                }
        }
        __syncthreads();
    }
#pragma unroll
    for (int i = 0; i < 4; i++)
#pragma unroll
        for (int j = 0; j < 4; j++) {
            int r = m0 + ty * 4 + i, c = n0 + tx * 4 + j;
            float v = 0.5f * (s[i][j] + cmp[i][j]);
            if (r == c) v += EPSc;
            P[(size_t)r * NXc + c] = v;
        }
}

// ---------------- power iteration (lambda_max estimate) ----------------
__global__ void k_pow_init(float* __restrict__ v) { v[threadIdx.x] = 1.f; }

__global__ void k_gemv(const float* __restrict__ P, const float* __restrict__ v,
                       float* __restrict__ w) {
    __shared__ float sm[128];
    int r = blockIdx.x;
    float s = 0.f;
    for (int k = threadIdx.x; k < NXc; k += 128)
        s = fmaf(P[(size_t)r * NXc + k], v[k], s);
    sm[threadIdx.x] = s;
    __syncthreads();
    for (int o = 64; o > 0; o >>= 1) {
        if (threadIdx.x < o) sm[threadIdx.x] += sm[threadIdx.x + o];
        __syncthreads();
    }
    if (threadIdx.x == 0) w[r] = sm[0];
}

__global__ void k_nrm(const float* __restrict__ w, float* __restrict__ v,
                      float* __restrict__ lam) {
    __shared__ float sm[512];
    int t = threadIdx.x;
    float x = w[t];
    sm[t] = x * x;
    __syncthreads();
    for (int o = 256; o > 0; o >>= 1) {
        if (t < o) sm[t] += sm[t + o];
        __syncthreads();
    }
    __shared__ float nsh;
    if (t == 0) { nsh = sqrtf(sm[0]); lam[0] = nsh; }
    __syncthreads();
    v[t] = x / nsh;
}

// seed: X0 = a*(2I - a*P), a = 2/(1.25*lam_hat)
__global__ void k_newton_init(const float* __restrict__ P, float* __restrict__ X0,
                              const float* __restrict__ lam) {
    int idx = blockIdx.x * 256 + threadIdx.x;
    float a = 2.f / (1.25f * lam[0]);
    int i = idx >> 9, j = idx & 511;
    float v = -a * a * P[idx];
    if (i == j) v += 2.f * a;
    X0[idx] = v;
}

__global__ void k_combine(const float* __restrict__ X, float* __restrict__ Pinv) {
    int idx = blockIdx.x * 256 + threadIdx.x;
    Pinv[idx] = X[idx] + X[NN + idx];
}

// ---------------- small elementwise builders ----------------
__global__ void k_rlam(const float* __restrict__ H4, float* __restrict__ rlam) {
    int i = blockIdx.x * 256 + threadIdx.x;
    if (i < NQc) rlam[i] = 1.f / (0.5f * (H4[(size_t)i * NQc + i] + EPSc));
}

__global__ void k_D11(const float* __restrict__ H4, const float* __restrict__ rlam,
                      float* __restrict__ D11) {
    int idx = blockIdx.x * 256 + threadIdx.x;
    int i = idx >> 9, j = idx & 511;
    D11[idx] = (j < i) ? (-H4[idx] * rlam[i]) : 0.f;
}

// YM = [Y | M]; Y = -0.5*(H1 + eps*I + Y1 - Y1^T), M = -H2 - Chi
__global__ void k_build_YM(const float* __restrict__ H12, const float* __restrict__ Y1,
                           const float* __restrict__ Chi, float* __restrict__ YM) {
    int idx = blockIdx.x * 256 + threadIdx.x;
    int i = idx >> 10, j = idx & 1023;
    float v;
    if (j < NXc) {
        v = H12[(size_t)i * 1024 + j] + Y1[(size_t)i * NXc + j] - Y1[(size_t)j * NXc + i];
        if (i == j) v += EPSc;
        v = -0.5f * v;
    } else {
        int jm = j - NXc;
        v = -H12[(size_t)i * 1024 + j] - Chi[(size_t)i * NQc + jm];
    }
    YM[(size_t)i * 1024 + j] = v;
}

__global__ void k_build_CD(const float* __restrict__ Chi, const float* __restrict__ D12,
                           const float* __restrict__ rlam, float* __restrict__ CD) {
    int q = blockIdx.x, k = threadIdx.x;
    float v = (k < NXc) ? Chi[(size_t)k * NQc + q] * rlam[q]
                        : D12[(size_t)q * NUc + (k - NXc)];
    CD[(size_t)q * KXU + k] = v;
}

__global__ void k_build_AB2(const float* __restrict__ AmB1, const float* __restrict__ B2,
                            float* __restrict__ AB2) {
    int x = blockIdx.x, k = threadIdx.x;
    float v = (k < NXc) ? AmB1[(size_t)x * 1024 + k]
                        : B2[(size_t)x * NUc + (k - NXc)];
    AB2[(size_t)x * KXU + k] = v;
}

__global__ void k_build_xu(const float* __restrict__ xi, const float* __restrict__ u,
                           float* __restrict__ xu) {
    size_t idx = (size_t)blockIdx.x * 256 + threadIdx.x;
    int b = (int)(idx / KXU), k = (int)(idx % KXU);
    xu[idx] = (k < NXc) ? xi[(size_t)b * NXc + k] : u[(size_t)b * NUc + (k - NXc)];
}

// ---------------- within-chunk sequential tanh scan ----------------
__global__ __launch_bounds__(256)
void k_scan(const float* __restrict__ baseT, float* __restrict__ wT,
            const float* __restrict__ D11, int c) {
    __shared__ float d[64][65];
    const int tid = threadIdx.x;
    const size_t b = (size_t)blockIdx.x * 256 + tid;
    const int r0 = c * 64;
    for (int idx = tid; idx < 4096; idx += 256) {
        int i = idx >> 6, j = idx & 63;
        d[i][j] = D11[(size_t)(r0 + i) * NQc + r0 + j];
    }
    __syncthreads();
    float w[64];
#pragma unroll
    for (int i = 0; i < 64; i++) {
        size_t off = (size_t)(r0 + i) * B_SZ + b;
        float v = baseT[off];
        if (c > 0) v += wT[off];
        float s0 = 0.f, s1 = 0.f, s2 = 0.f, s3 = 0.f;
#pragma unroll
        for (int j = 0; j + 3 < i; j += 4) {
            s0 = fmaf(w[j],     d[i][j],     s0);
            s1 = fmaf(w[j + 1], d[i][j + 1], s1);
            s2 = fmaf(w[j + 2], d[i][j + 2], s2);
            s3 = fmaf(w[j + 3], d[i][j + 3], s3);
        }
#pragma unroll
        for (int j = i & ~3; j < i; j++) s0 = fmaf(w[j], d[i][j], s0);
        v += (s0 + s1) + (s2 + s3);
        v = tanhf(v);
        w[i] = v;
        wT[off] = v;
    }
}

// ---------------- host-side launch helpers ----------------
template <int BM, int BN, int BK, int TM, int TN, bool TRA, bool TRB>
static void launch_gemm(int M, int N, int K,
                        const float* A, int lda, const float* B, int ldb,
                        float* C, int ldc, float alpha, float beta) {
    dim3 grid(N / BN, M / BM);
    sgemm_kernel<BM, BN, BK, TM, TN, TRA, TRB>
        <<<grid, (BM / TM) * (BN / TN)>>>(M, N, K, A, lda, B, ldb, C, ldc, alpha, beta);
}

#define G64(TRA, TRB)   launch_gemm<64, 64, 16, 4, 4, TRA, TRB>
#define G64W(TRA, TRB)  launch_gemm<64, 128, 16, 4, 8, TRA, TRB>
#define G128(TRA, TRB)  launch_gemm<128, 128, 16, 8, 8, TRA, TRB>

static float* sym(const void* symbol) {
    void* p = nullptr;
    cudaGetSymbolAddress(&p, symbol);
    return (float*)p;
}

extern "C" void kernel_launch(void* const* d_in, const int* in_sizes, int n_in,
                              void* d_out, int out_size) {
    const float* xi    = (const float*)d_in[1];
    const float* u     = (const float*)d_in[2];
    const float* Pstar = (const float*)d_in[3];
    const float* Chi   = (const float*)d_in[4];
    const float* Y1    = (const float*)d_in[5];
    const float* B2    = (const float*)d_in[6];
    const float* D12   = (const float*)d_in[7];
    const float* X     = (const float*)d_in[8];
    float* out = (float*)d_out;

    float* P    = sym(g_P);
    float* T2   = sym(g_T2);
    float* NXa  = sym(g_NXa);
    float* NXb  = sym(g_NXb);
    float* Pinv = sym(g_Pinv);
    float* H12  = sym(g_H12);
    float* H4   = sym(g_H4);
    float* YM   = sym(g_YM);
    float* AmB1 = sym(g_AmB1);
    float* D11  = sym(g_D11);
    float* CD   = sym(g_CD);
    float* AB2  = sym(g_AB2);
    float* rlam = sym(g_rlam);
    float* xu   = sym(g_xu);
    float* baseT = sym(g_baseT);
    float* wT   = sym(g_wT);
    float* pv   = sym(g_pv);
    float* pw   = sym(g_pw);
    float* lam  = sym(g_lam);

    // ---- P = 0.5*Pstar@Pstar^T + eps*I (compensated) ----
    pgemm_dot2_kernel<<<dim3(8, 8), 256>>>(Pstar, P);

    // ---- lambda_max estimate via power iteration ----
    k_pow_init<<<1, NXc>>>(pv);
    for (int it = 0; it < NPOW; it++) {
        k_gemv<<<NXc, 128>>>(P, pv, pw);
        k_nrm<<<1, NXc>>>(pw, pv, lam);
    }

    // ---- Newton-Schulz: seed + 16 split-K iterations ----
    k_newton_init<<<NN / 256, 256>>>(P, NXa, lam);
    cudaMemsetAsync(NXa + NN, 0, NN * sizeof(float));
    float* Xc = NXa;
    float* Xn = NXb;
    dim3 ngrid(8, 8, 2);
    for (int it = 0; it < NEWTON_ITERS; it++) {
        newton_gemm<false, false><<<ngrid, 256>>>(P, P, Xc, Xc + NN, T2);
        newton_gemm<true,  true ><<<ngrid, 256>>>(Xc, Xc + NN, T2, T2 + NN, Xn);
        float* tmp = Xc; Xc = Xn; Xn = tmp;
    }
    k_combine<<<NN / 256, 256>>>(Xc, Pinv);

    // ---- H blocks: [H1|H2] = X_hi @ X^T (one GEMM), H4 = X_lo @ X_lo^T ----
    const float* Xlo = X + (size_t)NXc * 1024;
    G64(false, true)(NXc, 1024, 1024, X, 1024, X, 1024, H12, 1024, 1.f, 0.f);
    G64(false, true)(NQc, NQc, 1024, Xlo, 1024, Xlo, 1024, H4, NQc, 1.f, 0.f);

    // ---- derived small matrices ----
    k_rlam<<<2, 256>>>(H4, rlam);
    k_D11<<<1024, 256>>>(H4, rlam, D11);
    k_build_YM<<<2048, 256>>>(H12, Y1, Chi, YM);
    // [A | B1] = Pinv @ [Y | M]
    G64(false, false)(NXc, 1024, NXc, Pinv, NXc, YM, 1024, AmB1, 1024, 1.f, 0.f);
    k_build_CD<<<NQc, KXU>>>(Chi, D12, rlam, CD);
    k_build_AB2<<<NXc, KXU>>>(AmB1, B2, AB2);

    // ---- batched path ----
    k_build_xu<<<(B_SZ * KXU) / 256, 256>>>(xi, u, xu);
    G128(false, true)(NQc, B_SZ, KXU, CD, KXU, xu, KXU, baseT, B_SZ, 1.f, 0.f);

    // ---- chunked recurrence: 8 chunks of 64 ----
    for (int c = 0; c < 8; c++) {
        if (c > 0) {
            G64W(false, false)(64, B_SZ, c * 64,
                               D11 + (size_t)c * 64 * NQc, NQc,
                               wT, B_SZ,
                               wT + (size_t)c * 64 * B_SZ, B_SZ, 1.f, 0.f);
        }
        k_scan<<<B_SZ / 256, 256>>>(baseT, wT, D11, c);
    }

    // ---- output: out = xu @ AB2^T + wT^T @ B1^T ----
    G128(false, true)(B_SZ, NXc, KXU, xu, KXU, AB2, KXU, out, NXc, 1.f, 0.f);
    G128(true, true)(B_SZ, NXc, NQc, wT, B_SZ, AmB1 + NXc, 1024, out, NXc, 1.f, 1.f);
}